// round 6
// baseline (speedup 1.0000x reference)
#include <cuda_runtime.h>
#include <math.h>

#define BB 8
#define NN 8192
#define HH 32
#define WW 32
#define DD 256
#define HW (HH * WW)                 // 1024
#define ZQ_SIZE (BB * DD * HH * WW)  // 2097152
#define NPOS (BB * HH * WW)          // 8192
#define NGRP 256                     // (b,h) groups
#define NQ 4                         // n-quarters per group
#define NBLK4 (NGRP * NQ)            // 1024 CTAs
#define KLW 5e-4f
#define LOG_N 9.010913347279288f     // log(8192)

// cross-CTA scratch (device globals; no allocation)
__device__ float        g_pm1[NBLK4][32];
__device__ int          g_pa1[NBLK4][32];
__device__ float        g_pS [NBLK4][32];
__device__ float        g_pT [NBLK4][32];
__device__ float        g_kl_partial[NGRP];
__device__ unsigned int g_group[NGRP];         // per-(b,h) arrival, self-reset
__device__ unsigned int g_arrive = 0;          // combiner arrival, self-reset

__global__ void __launch_bounds__(128, 7)
gumbel_fused_kernel(const float* __restrict__ z,
                    const float* __restrict__ Wt,
                    const float* __restrict__ g,
                    float* __restrict__ out)
{
    const int bidx = blockIdx.x;     // 0..1023
    const int bh   = bidx >> 2;      // (b,h)
    const int q    = bidx & 3;       // n-quarter
    const int b    = bh >> 5;
    const int h    = bh & 31;
    const int tid  = threadIdx.x;    // 0..127
    const int w    = tid & 31;       // lane = w (full 128B rows)
    const int wn   = tid >> 5;       // warp 0..3

    // smem: warp stats (2KB) overlaid by gather staging (16.5KB)
    __shared__ __align__(16) unsigned char s_buf[32 * 129 * 4];  // 16512B
    float (*s_m1)[32] = (float (*)[32])(s_buf);
    int   (*s_a1)[32] = (int   (*)[32])(s_buf + 512);
    float (*s_S )[32] = (float (*)[32])(s_buf + 1024);
    float (*s_T )[32] = (float (*)[32])(s_buf + 1536);
    float (*s_rows)[129] = (float (*)[129])(s_buf);   // 32 rows x 128 d-half
    __shared__ int   s_ind[32];
    __shared__ bool  s_last, s_fin;

    // n rows handled by this thread: n = q*2048 + wn + i*4, i = 0..511
    const int n0 = q * 2048 + wn;
    const long long base = (long long)(b * NN + n0) * HW + h * WW + w;
    const float* zp = z + base;
    const float* gp = g + base;
    const int stride = 4 * HW;       // floats per iteration

    float m1 = -INFINITY; int a1 = 0;
    float S = 0.f, T = 0.f;

    #pragma unroll 8
    for (int i = 0; i < 512; ++i) {
        const float zv = __ldg(zp + (long long)i * stride);
        const float gv = __ldg(gp + (long long)i * stride);
        const float lg = zv + gv;
        if (lg > m1) { m1 = lg; a1 = n0 + i * 4; }
        const float e = __expf(zv);          // z ~ N(0,1): shift-free is safe
        S += e;
        T = fmaf(e, zv, T);
    }

    s_m1[wn][w] = m1; s_a1[wn][w] = a1; s_S[wn][w] = S; s_T[wn][w] = T;
    __syncthreads();

    // warp 0 combines 4 warps, writes this CTA's partial to global scratch
    if (tid < 32) {
        float M1 = s_m1[0][w]; int A1 = s_a1[0][w];
        float SS = s_S[0][w];  float TT = s_T[0][w];
        #pragma unroll
        for (int i = 1; i < 4; ++i) {
            const float v = s_m1[i][w]; const int a = s_a1[i][w];
            if (v > M1 || (v == M1 && a < A1)) { M1 = v; A1 = a; }
            SS += s_S[i][w];
            TT += s_T[i][w];
        }
        g_pm1[bidx][w] = M1; g_pa1[bidx][w] = A1;
        g_pS [bidx][w] = SS; g_pT [bidx][w] = TT;
    }
    __syncthreads();

    if (tid == 0) {
        __threadfence();
        const unsigned old = atomicAdd(&g_group[bh], 1u);
        s_last = (old == NQ - 1);
    }
    __syncthreads();
    if (!s_last) return;             // non-combiner CTAs are done
    __threadfence();                 // acquire: partials of peers visible

    // ---- combiner: finalize (b,h): argmax/KL over 4 quarters ----
    if (tid < 32) {
        float M1 = g_pm1[bh * 4][w]; int A1 = g_pa1[bh * 4][w];
        float SS = g_pS[bh * 4][w];  float TT = g_pT[bh * 4][w];
        #pragma unroll
        for (int j = 1; j < NQ; ++j) {
            const int p = bh * 4 + j;
            const float v = g_pm1[p][w]; const int a = g_pa1[p][w];
            if (v > M1 || (v == M1 && a < A1)) { M1 = v; A1 = a; }
            SS += g_pS[p][w];
            TT += g_pT[p][w];
        }
        float kl = TT / SS - __logf(SS) + LOG_N;

        s_ind[w] = A1;
        out[ZQ_SIZE + 1 + bh * 32 + w] = (float)A1;

        #pragma unroll
        for (int off = 16; off; off >>= 1)
            kl += __shfl_xor_sync(0xffffffffu, kl, off);
        if (w == 0) {
            g_kl_partial[bh] = kl;
            g_group[bh] = 0;                 // reset for next replay
        }
    }
    __syncthreads();                 // stats scratch free -> reuse as s_rows

    // ---- z_q gather + transposed write, staged in two d-halves ----
    const int obase = (b * DD) * HW + h * WW + w;
    #pragma unroll
    for (int halfd = 0; halfd < 2; ++halfd) {
        const int d0 = halfd * 128;
        #pragma unroll 4
        for (int r = 0; r < 32; ++r)
            s_rows[r][tid] = __ldg(Wt + s_ind[r] * DD + d0 + tid);
        __syncthreads();
        #pragma unroll 8
        for (int k = 0; k < 32; ++k) {
            const int dl = wn * 32 + k;      // 4 warps x 32 = 128 d-local
            out[obase + (long long)(d0 + dl) * HW] = s_rows[w][dl];
        }
        __syncthreads();
    }

    // ---- final scalar: last combiner reduces 256 KL partials ----
    if (tid == 0) {
        __threadfence();
        const unsigned old = atomicAdd(&g_arrive, 1u);
        s_fin = (old == NGRP - 1);
    }
    __syncthreads();
    if (s_fin) {
        __threadfence();
        float v = g_kl_partial[tid] + g_kl_partial[tid + 128];
        #pragma unroll
        for (int off = 16; off; off >>= 1)
            v += __shfl_xor_sync(0xffffffffu, v, off);
        __shared__ float s_red[4];
        if ((tid & 31) == 0) s_red[tid >> 5] = v;
        __syncthreads();
        if (tid < 4) {
            float x = s_red[tid];
            #pragma unroll
            for (int off = 2; off; off >>= 1)
                x += __shfl_xor_sync(0x0000000fu, x, off, 4);
            if (tid == 0) {
                out[ZQ_SIZE] = KLW * (x / (float)NPOS);
                g_arrive = 0;                // reset for next replay
            }
        }
    }
}

extern "C" void kernel_launch(void* const* d_in, const int* in_sizes, int n_in,
                              void* d_out, int out_size)
{
    const float* z  = (const float*)d_in[0];
    const float* Wt = (const float*)d_in[1];
    const float* g  = (const float*)d_in[2];
    float* out = (float*)d_out;

    gumbel_fused_kernel<<<NBLK4, 128>>>(z, Wt, g, out);
}

// round 7
// speedup vs baseline: 1.3119x; 1.3119x over previous
#include <cuda_runtime.h>
#include <math.h>

#define BB 8
#define NN 8192
#define HH 32
#define WW 32
#define DD 256
#define HW (HH * WW)                 // 1024
#define ZQ_SIZE (BB * DD * HH * WW)  // 2097152
#define NPOS (BB * HH * WW)          // 8192
#define NGRP 256                     // (b,h) groups
#define NQ 4                         // n-quarters per group
#define NBLK4 (NGRP * NQ)            // 1024 CTAs
#define KLW 5e-4f
#define LOG_N 9.010913347279288f     // log(8192)

// cross-CTA scratch (device globals; no allocation)
__device__ float        g_pm1[NBLK4][32];
__device__ int          g_pa1[NBLK4][32];
__device__ float        g_pS [NBLK4][32];
__device__ float        g_pT [NBLK4][32];
__device__ float        g_kl_partial[NGRP];
__device__ unsigned int g_group[NGRP];         // per-(b,h) arrival, self-reset
__device__ unsigned int g_arrive = 0;          // combiner arrival, self-reset

__global__ void __launch_bounds__(128, 7)
gumbel_fused_kernel(const float* __restrict__ z,
                    const float* __restrict__ Wt,
                    const float* __restrict__ g,
                    float* __restrict__ out)
{
    const int bidx = blockIdx.x;     // 0..1023
    const int bh   = bidx >> 2;      // (b,h)
    const int q    = bidx & 3;       // n-quarter
    const int b    = bh >> 5;
    const int h    = bh & 31;
    const int tid  = threadIdx.x;    // 0..127
    const int grp  = tid & 7;        // w-quad: w = grp*4..grp*4+3 (full 128B/warp row)
    const int np   = tid >> 3;       // n-partition 0..15

    // smem: stats (8KB, phase 1-2) overlaid by gather staging (16.5KB, phase 3)
    __shared__ __align__(16) unsigned char s_buf[32 * 129 * 4];  // 16512B
    float (*s_m1)[32] = (float (*)[32])(s_buf);            // [16][32] 2KB
    int   (*s_a1)[32] = (int   (*)[32])(s_buf + 2048);
    float (*s_S )[32] = (float (*)[32])(s_buf + 4096);
    float (*s_T )[32] = (float (*)[32])(s_buf + 6144);
    float (*s_rows)[129] = (float (*)[129])(s_buf);        // 32 rows x 128 d-half
    __shared__ int   s_ind[32];
    __shared__ bool  s_last, s_fin;

    // thread's n rows: n = q*2048 + np + i*16, i = 0..127
    const int n0 = q * 2048 + np;
    const long long base = (long long)(b * NN + n0) * HW + h * WW + grp * 4;
    const float4* zp = (const float4*)(z + base);
    const float4* gp = (const float4*)(g + base);
    const int strideV = 16 * HW / 4;          // float4 units per iteration

    float m1x=-INFINITY, m1y=-INFINITY, m1z=-INFINITY, m1w=-INFINITY;
    int   a1x=0, a1y=0, a1z=0, a1w=0;
    float Sx=0.f, Sy=0.f, Sz=0.f, Sw=0.f;
    float Tx=0.f, Ty=0.f, Tz=0.f, Tw=0.f;

    #pragma unroll 4
    for (int i = 0; i < 128; ++i) {
        const int n = n0 + i * 16;
        const float4 zv = __ldg(zp + (long long)i * strideV);
        const float4 gv = __ldg(gp + (long long)i * strideV);

        // argmax of z+g (strict > keeps first index, like jnp.argmax)
        float lg;
        lg = zv.x + gv.x; if (lg > m1x) { m1x = lg; a1x = n; }
        lg = zv.y + gv.y; if (lg > m1y) { m1y = lg; a1y = n; }
        lg = zv.z + gv.z; if (lg > m1z) { m1z = lg; a1z = n; }
        lg = zv.w + gv.w; if (lg > m1w) { m1w = lg; a1w = n; }

        // shift-free softmax stats: z ~ N(0,1) -> exp safe in fp32
        float e;
        e = __expf(zv.x); Sx += e; Tx = fmaf(e, zv.x, Tx);
        e = __expf(zv.y); Sy += e; Ty = fmaf(e, zv.y, Ty);
        e = __expf(zv.z); Sz += e; Tz = fmaf(e, zv.z, Tz);
        e = __expf(zv.w); Sw += e; Tw = fmaf(e, zv.w, Tw);
    }

    const int w0 = grp * 4;
    s_m1[np][w0+0]=m1x; s_m1[np][w0+1]=m1y; s_m1[np][w0+2]=m1z; s_m1[np][w0+3]=m1w;
    s_a1[np][w0+0]=a1x; s_a1[np][w0+1]=a1y; s_a1[np][w0+2]=a1z; s_a1[np][w0+3]=a1w;
    s_S [np][w0+0]=Sx;  s_S [np][w0+1]=Sy;  s_S [np][w0+2]=Sz;  s_S [np][w0+3]=Sw;
    s_T [np][w0+0]=Tx;  s_T [np][w0+1]=Ty;  s_T [np][w0+2]=Tz;  s_T [np][w0+3]=Tw;
    __syncthreads();

    // warp 0 (one lane per w) combines 16 partitions, writes CTA partial
    if (tid < 32) {
        const int w = tid;
        float M1 = s_m1[0][w]; int A1 = s_a1[0][w];
        float SS = s_S[0][w];  float TT = s_T[0][w];
        #pragma unroll
        for (int i = 1; i < 16; ++i) {
            const float v = s_m1[i][w]; const int a = s_a1[i][w];
            if (v > M1 || (v == M1 && a < A1)) { M1 = v; A1 = a; }
            SS += s_S[i][w];
            TT += s_T[i][w];
        }
        g_pm1[bidx][w] = M1; g_pa1[bidx][w] = A1;
        g_pS [bidx][w] = SS; g_pT [bidx][w] = TT;
    }
    __syncthreads();

    if (tid == 0) {
        __threadfence();
        const unsigned old = atomicAdd(&g_group[bh], 1u);
        s_last = (old == NQ - 1);
    }
    __syncthreads();
    if (!s_last) return;             // non-combiner CTAs are done
    __threadfence();                 // acquire: peer partials visible

    // ---- combiner: finalize (b,h): argmax/KL over 4 quarters ----
    if (tid < 32) {
        const int w = tid;
        float M1 = g_pm1[bh * 4][w]; int A1 = g_pa1[bh * 4][w];
        float SS = g_pS[bh * 4][w];  float TT = g_pT[bh * 4][w];
        #pragma unroll
        for (int j = 1; j < NQ; ++j) {
            const int p = bh * 4 + j;
            const float v = g_pm1[p][w]; const int a = g_pa1[p][w];
            if (v > M1 || (v == M1 && a < A1)) { M1 = v; A1 = a; }
            SS += g_pS[p][w];
            TT += g_pT[p][w];
        }
        float kl = TT / SS - __logf(SS) + LOG_N;

        s_ind[w] = A1;
        out[ZQ_SIZE + 1 + bh * 32 + w] = (float)A1;

        #pragma unroll
        for (int off = 16; off; off >>= 1)
            kl += __shfl_xor_sync(0xffffffffu, kl, off);
        if (w == 0) {
            g_kl_partial[bh] = kl;
            g_group[bh] = 0;                 // reset for next replay
        }
    }
    __syncthreads();                 // stats scratch free -> reuse as s_rows

    // ---- z_q gather + transposed write, staged in two d-halves ----
    {
        const int wl = tid & 31;
        const int wn = tid >> 5;     // 4 warps
        const long long obase = (long long)(b * DD) * HW + h * WW + wl;
        #pragma unroll
        for (int halfd = 0; halfd < 2; ++halfd) {
            const int d0 = halfd * 128;
            #pragma unroll 4
            for (int r = 0; r < 32; ++r)
                s_rows[r][tid] = __ldg(Wt + s_ind[r] * DD + d0 + tid);
            __syncthreads();
            #pragma unroll 8
            for (int k = 0; k < 32; ++k) {
                const int dl = wn * 32 + k;  // 4 warps x 32 = 128 d-local
                out[obase + (long long)(d0 + dl) * HW] = s_rows[wl][dl];
            }
            __syncthreads();
        }
    }

    // ---- final scalar: last combiner reduces 256 KL partials ----
    if (tid == 0) {
        __threadfence();
        const unsigned old = atomicAdd(&g_arrive, 1u);
        s_fin = (old == NGRP - 1);
    }
    __syncthreads();
    if (s_fin) {
        __threadfence();
        float v = g_kl_partial[tid] + g_kl_partial[tid + 128];
        #pragma unroll
        for (int off = 16; off; off >>= 1)
            v += __shfl_xor_sync(0xffffffffu, v, off);
        __shared__ float s_red[4];
        if ((tid & 31) == 0) s_red[tid >> 5] = v;
        __syncthreads();
        if (tid < 4) {
            float x = s_red[tid];
            #pragma unroll
            for (int off = 2; off; off >>= 1)
                x += __shfl_xor_sync(0x0000000fu, x, off, 4);
            if (tid == 0) {
                out[ZQ_SIZE] = KLW * (x / (float)NPOS);
                g_arrive = 0;                // reset for next replay
            }
        }
    }
}

extern "C" void kernel_launch(void* const* d_in, const int* in_sizes, int n_in,
                              void* d_out, int out_size)
{
    const float* z  = (const float*)d_in[0];
    const float* Wt = (const float*)d_in[1];
    const float* g  = (const float*)d_in[2];
    float* out = (float*)d_out;

    gumbel_fused_kernel<<<NBLK4, 128>>>(z, Wt, g, out);
}

// round 8
// speedup vs baseline: 1.3625x; 1.0386x over previous
#include <cuda_runtime.h>
#include <math.h>

#define BB 8
#define NN 8192
#define HH 32
#define WW 32
#define DD 256
#define HW (HH * WW)                 // 1024
#define ZQ_SIZE (BB * DD * HH * WW)  // 2097152
#define NPOS (BB * HH * WW)          // 8192
#define NGID 512                     // (b,h,w-half) groups
#define NBLK5 1024                   // x n-half
#define KLW 5e-4f
#define LOG_N 9.010913347279288f     // log(8192)

// cross-CTA scratch (device globals; no allocation)
__device__ float        g_pm1[NBLK5][16];
__device__ int          g_pa1[NBLK5][16];
__device__ float        g_pS [NBLK5][16];
__device__ float        g_pT [NBLK5][16];
__device__ float        g_kl_partial[NGID];
__device__ unsigned int g_pair[NGID];          // per-group arrival, self-reset
__device__ unsigned int g_arrive = 0;          // final arrival, self-reset

__global__ void __launch_bounds__(256, 4)
gumbel_fused_kernel(const float* __restrict__ z,
                    const float* __restrict__ Wt,
                    const float* __restrict__ g,
                    float* __restrict__ out)
{
    const int bidx  = blockIdx.x;    // 0..1023
    const int gid   = bidx >> 1;     // (b,h,w-half) 0..511
    const int nh    = bidx & 1;      // n-half
    const int bh    = gid >> 1;      // (b,h)
    const int whalf = gid & 1;
    const int b     = bh >> 5;
    const int h     = bh & 31;
    const int tid   = threadIdx.x;   // 0..255
    const int grp   = tid & 3;       // w-quad within half: local w = grp*4..+3
    const int np    = tid >> 2;      // n-partition 0..63

    // smem: stats (16KB, phase 1-2) overlaid by gather rows (16.4KB, phase 3)
    __shared__ __align__(16) unsigned char s_buf[16 * 257 * 4];  // 16448B
    float (*s_m1)[16] = (float (*)[16])(s_buf);            // [64][16] 4KB
    int   (*s_a1)[16] = (int   (*)[16])(s_buf + 4096);
    float (*s_S )[16] = (float (*)[16])(s_buf + 8192);
    float (*s_T )[16] = (float (*)[16])(s_buf + 12288);
    float (*s_rows)[DD + 1] = (float (*)[DD + 1])(s_buf);  // [16][257]
    __shared__ int   s_ind[16];
    __shared__ bool  s_last, s_fin;

    // thread rows: n = nh*4096 + np + i*64, i = 0..63
    const int n0 = nh * 4096 + np;
    const long long base =
        (long long)(b * NN + n0) * HW + h * WW + whalf * 16 + grp * 4;
    const float4* zp = (const float4*)(z + base);
    const float4* gp = (const float4*)(g + base);
    const int strideV = 64 * HW / 4;          // float4 units per iteration

    float m1x=-INFINITY, m1y=-INFINITY, m1z=-INFINITY, m1w=-INFINITY;
    int   a1x=0, a1y=0, a1z=0, a1w=0;
    float Sx=0.f, Sy=0.f, Sz=0.f, Sw=0.f;
    float Tx=0.f, Ty=0.f, Tz=0.f, Tw=0.f;

    #pragma unroll 2
    for (int i = 0; i < 64; ++i) {
        const int n = n0 + i * 64;
        const float4 zv = __ldg(zp + (long long)i * strideV);
        const float4 gv = __ldg(gp + (long long)i * strideV);

        // argmax of z+g (strict > keeps first index, like jnp.argmax)
        float lg;
        lg = zv.x + gv.x; if (lg > m1x) { m1x = lg; a1x = n; }
        lg = zv.y + gv.y; if (lg > m1y) { m1y = lg; a1y = n; }
        lg = zv.z + gv.z; if (lg > m1z) { m1z = lg; a1z = n; }
        lg = zv.w + gv.w; if (lg > m1w) { m1w = lg; a1w = n; }

        // shift-free softmax stats: z ~ N(0,1) -> exp safe in fp32
        float e;
        e = __expf(zv.x); Sx += e; Tx = fmaf(e, zv.x, Tx);
        e = __expf(zv.y); Sy += e; Ty = fmaf(e, zv.y, Ty);
        e = __expf(zv.z); Sz += e; Tz = fmaf(e, zv.z, Tz);
        e = __expf(zv.w); Sw += e; Tw = fmaf(e, zv.w, Tw);
    }

    const int w0 = grp * 4;
    s_m1[np][w0+0]=m1x; s_m1[np][w0+1]=m1y; s_m1[np][w0+2]=m1z; s_m1[np][w0+3]=m1w;
    s_a1[np][w0+0]=a1x; s_a1[np][w0+1]=a1y; s_a1[np][w0+2]=a1z; s_a1[np][w0+3]=a1w;
    s_S [np][w0+0]=Sx;  s_S [np][w0+1]=Sy;  s_S [np][w0+2]=Sz;  s_S [np][w0+3]=Sw;
    s_T [np][w0+0]=Tx;  s_T [np][w0+1]=Ty;  s_T [np][w0+2]=Tz;  s_T [np][w0+3]=Tw;
    __syncthreads();

    // first 16 threads combine 64 partitions -> CTA partial to global scratch
    if (tid < 16) {
        const int wl = tid;
        float M1 = s_m1[0][wl]; int A1 = s_a1[0][wl];
        float SS = s_S[0][wl];  float TT = s_T[0][wl];
        #pragma unroll
        for (int i = 1; i < 64; ++i) {
            const float v = s_m1[i][wl]; const int a = s_a1[i][wl];
            if (v > M1 || (v == M1 && a < A1)) { M1 = v; A1 = a; }
            SS += s_S[i][wl];
            TT += s_T[i][wl];
        }
        g_pm1[bidx][wl] = M1; g_pa1[bidx][wl] = A1;
        g_pS [bidx][wl] = SS; g_pT [bidx][wl] = TT;
    }
    __syncthreads();

    if (tid == 0) {
        __threadfence();
        const unsigned old = atomicAdd(&g_pair[gid], 1u);
        s_last = (old == 1);
    }
    __syncthreads();
    if (!s_last) return;             // non-combiner CTA done
    __threadfence();                 // acquire: peer partial visible

    // ---- combiner: finalize this (b,h,w-half) ----
    if (tid < 16) {
        const int wl = tid;
        float M1 = g_pm1[gid * 2][wl]; int A1 = g_pa1[gid * 2][wl];
        float SS = g_pS[gid * 2][wl];  float TT = g_pT[gid * 2][wl];
        {
            const int p = gid * 2 + 1;
            const float v = g_pm1[p][wl]; const int a = g_pa1[p][wl];
            if (v > M1 || (v == M1 && a < A1)) { M1 = v; A1 = a; }
            SS += g_pS[p][wl];
            TT += g_pT[p][wl];
        }
        float kl = TT / SS - __logf(SS) + LOG_N;

        s_ind[wl] = A1;
        out[ZQ_SIZE + 1 + bh * 32 + whalf * 16 + wl] = (float)A1;

        #pragma unroll
        for (int off = 8; off; off >>= 1)
            kl += __shfl_xor_sync(0x0000ffffu, kl, off, 16);
        if (wl == 0) {
            g_kl_partial[gid] = kl;
            g_pair[gid] = 0;                 // reset for next replay
        }
    }
    __syncthreads();                 // stats free -> reuse as s_rows

    // ---- z_q gather (16 rows x 256 d) + transposed write ----
    #pragma unroll 4
    for (int r = 0; r < 16; ++r)
        s_rows[r][tid] = __ldg(Wt + s_ind[r] * DD + tid);
    __syncthreads();

    {
        const int wl = tid & 15;
        const int dn = tid >> 4;     // 16 d-groups of 16
        const long long obase =
            (long long)(b * DD) * HW + h * WW + whalf * 16 + wl;
        #pragma unroll 8
        for (int k = 0; k < 16; ++k) {
            const int d = dn * 16 + k;
            out[obase + (long long)d * HW] = s_rows[wl][d];
        }
    }

    // ---- final scalar: last combiner reduces 512 KL partials ----
    if (tid == 0) {
        __threadfence();
        const unsigned old = atomicAdd(&g_arrive, 1u);
        s_fin = (old == NGID - 1);
    }
    __syncthreads();
    if (s_fin) {
        __threadfence();
        float v = g_kl_partial[tid] + g_kl_partial[tid + 256];
        #pragma unroll
        for (int off = 16; off; off >>= 1)
            v += __shfl_xor_sync(0xffffffffu, v, off);
        __shared__ float s_red[8];
        if ((tid & 31) == 0) s_red[tid >> 5] = v;
        __syncthreads();
        if (tid < 8) {
            float x = s_red[tid];
            #pragma unroll
            for (int off = 4; off; off >>= 1)
                x += __shfl_xor_sync(0x000000ffu, x, off, 8);
            if (tid == 0) {
                out[ZQ_SIZE] = KLW * (x / (float)NPOS);
                g_arrive = 0;                // reset for next replay
            }
        }
    }
}

extern "C" void kernel_launch(void* const* d_in, const int* in_sizes, int n_in,
                              void* d_out, int out_size)
{
    const float* z  = (const float*)d_in[0];
    const float* Wt = (const float*)d_in[1];
    const float* g  = (const float*)d_in[2];
    float* out = (float*)d_out;

    gumbel_fused_kernel<<<NBLK5, 256>>>(z, Wt, g, out);
}

// round 9
// speedup vs baseline: 1.6456x; 1.2077x over previous
#include <cuda_runtime.h>
#include <math.h>

#define BB 8
#define NN 8192
#define HH 32
#define WW 32
#define DD 256
#define HW (HH * WW)                 // 1024
#define ZQ_SIZE (BB * DD * HH * WW)  // 2097152
#define NPOS (BB * HH * WW)          // 8192
#define NGRP 256                     // one CTA per (b,h)
#define KLW 5e-4f
#define LOG_N 9.010913347279288f     // log(8192)

__device__ float        g_kl_partial[NGRP];
__device__ unsigned int g_arrive = 0;          // self-resetting; replay-safe

__global__ void __launch_bounds__(512, 2)
gumbel_fused_kernel(const float* __restrict__ z,
                    const float* __restrict__ Wt,
                    const float* __restrict__ g,
                    float* __restrict__ out)
{
    const int bh  = blockIdx.x;      // 0..255 = (b,h)
    const int b   = bh >> 5;
    const int h   = bh & 31;
    const int tid = threadIdx.x;     // 0..511
    const int grp = tid & 7;         // w-quad: w = grp*4..+3 (warp covers all 32 w)
    const int np  = tid >> 3;        // n-partition 0..63

    // smem: stats 32KB (phases 1-2) overlaid by 16.5KB gather rows (phase 3)
    __shared__ __align__(16) unsigned char s_buf[64 * 32 * 4 * 4];  // 32KB
    float (*s_m1)[32] = (float (*)[32])(s_buf);             // [64][32] 8KB
    int   (*s_a1)[32] = (int   (*)[32])(s_buf + 8192);
    float (*s_S )[32] = (float (*)[32])(s_buf + 16384);
    float (*s_T )[32] = (float (*)[32])(s_buf + 24576);
    float (*s_rows)[129] = (float (*)[129])(s_buf);         // [32][129] 16.5KB
    __shared__ int   s_ind[32];
    __shared__ bool  s_fin;

    // thread rows: n = np + i*64, i = 0..127; warp-LDG = 4 full 128B lines
    const long long base = (long long)(b * NN + np) * HW + h * WW + grp * 4;
    const float4* zp = (const float4*)(z + base);
    const float4* gp = (const float4*)(g + base);
    const int strideV = 64 * HW / 4;          // float4 units per iteration

    float m1x=-INFINITY, m1y=-INFINITY, m1z=-INFINITY, m1w=-INFINITY;
    int   a1x=0, a1y=0, a1z=0, a1w=0;
    float Sx=0.f, Sy=0.f, Sz=0.f, Sw=0.f;
    float Tx=0.f, Ty=0.f, Tz=0.f, Tw=0.f;

    #pragma unroll 4
    for (int i = 0; i < 128; ++i) {
        const int n = np + i * 64;
        const float4 zv = __ldg(zp + (long long)i * strideV);
        const float4 gv = __ldg(gp + (long long)i * strideV);

        // argmax of z+g (strict > keeps first index, like jnp.argmax)
        float lg;
        lg = zv.x + gv.x; if (lg > m1x) { m1x = lg; a1x = n; }
        lg = zv.y + gv.y; if (lg > m1y) { m1y = lg; a1y = n; }
        lg = zv.z + gv.z; if (lg > m1z) { m1z = lg; a1z = n; }
        lg = zv.w + gv.w; if (lg > m1w) { m1w = lg; a1w = n; }

        // shift-free softmax stats: z ~ N(0,1) -> exp safe in fp32
        float e;
        e = __expf(zv.x); Sx += e; Tx = fmaf(e, zv.x, Tx);
        e = __expf(zv.y); Sy += e; Ty = fmaf(e, zv.y, Ty);
        e = __expf(zv.z); Sz += e; Tz = fmaf(e, zv.z, Tz);
        e = __expf(zv.w); Sw += e; Tw = fmaf(e, zv.w, Tw);
    }

    const int w0 = grp * 4;
    s_m1[np][w0+0]=m1x; s_m1[np][w0+1]=m1y; s_m1[np][w0+2]=m1z; s_m1[np][w0+3]=m1w;
    s_a1[np][w0+0]=a1x; s_a1[np][w0+1]=a1y; s_a1[np][w0+2]=a1z; s_a1[np][w0+3]=a1w;
    s_S [np][w0+0]=Sx;  s_S [np][w0+1]=Sy;  s_S [np][w0+2]=Sz;  s_S [np][w0+3]=Sw;
    s_T [np][w0+0]=Tx;  s_T [np][w0+1]=Ty;  s_T [np][w0+2]=Tz;  s_T [np][w0+3]=Tw;
    __syncthreads();

    // warp 0: lane w combines the 64 n-partitions for its (b,h,w)
    if (tid < 32) {
        const int w = tid;
        float M1 = s_m1[0][w]; int A1 = s_a1[0][w];
        float S = s_S[0][w];  float T = s_T[0][w];
        #pragma unroll 8
        for (int i = 1; i < 64; ++i) {
            const float v = s_m1[i][w]; const int a = s_a1[i][w];
            if (v > M1 || (v == M1 && a < A1)) { M1 = v; A1 = a; }
            S += s_S[i][w];
            T += s_T[i][w];
        }
        float kl = T / S - __logf(S) + LOG_N;

        s_ind[w] = A1;
        out[ZQ_SIZE + 1 + bh * 32 + w] = (float)A1;

        #pragma unroll
        for (int off = 16; off; off >>= 1)
            kl += __shfl_xor_sync(0xffffffffu, kl, off);
        if (w == 0) g_kl_partial[bh] = kl;
    }
    __syncthreads();                 // stats scratch free -> reuse as s_rows

    // ---- z_q gather + transposed write, staged in two d-halves ----
    {
        const int lane = tid & 31;
        const int wid  = tid >> 5;   // 16 warps
        const long long obase = (long long)(b * DD) * HW + h * WW + lane;
        #pragma unroll
        for (int halfd = 0; halfd < 2; ++halfd) {
            const int d0 = halfd * 128;
            // 16 warps x 2 rows each; each warp reads 128 floats/row coalesced
            #pragma unroll
            for (int r = wid; r < 32; r += 16) {
                const int row = s_ind[r];
                #pragma unroll
                for (int c = 0; c < 4; ++c)
                    s_rows[r][c * 32 + lane] =
                        __ldg(Wt + row * DD + d0 + c * 32 + lane);
            }
            __syncthreads();
            // write: lane = w (128B stores); 16 warps x 8 d each
            #pragma unroll 8
            for (int k = 0; k < 8; ++k) {
                const int dl = wid * 8 + k;          // 0..127 d-local
                out[obase + (long long)(d0 + dl) * HW] = s_rows[lane][dl];
            }
            __syncthreads();
        }
    }

    // ---- last-CTA finalize: reduce 256 KL partials ----
    if (tid == 0) {
        __threadfence();
        const unsigned old = atomicAdd(&g_arrive, 1u);
        s_fin = (old == NGRP - 1);
    }
    __syncthreads();
    if (s_fin) {
        __threadfence();
        if (tid < 256) {
            float v = g_kl_partial[tid];
            #pragma unroll
            for (int off = 16; off; off >>= 1)
                v += __shfl_xor_sync(0xffffffffu, v, off);
            __shared__ float s_red[8];
            if ((tid & 31) == 0) s_red[tid >> 5] = v;
            __syncwarp();
            if (tid == 0) {
                float x = 0.f;
                #pragma unroll
                for (int j = 0; j < 8; ++j) x += s_red[j];
                out[ZQ_SIZE] = KLW * (x / (float)NPOS);
                g_arrive = 0;                // reset for next replay
            }
        }
    }
}

extern "C" void kernel_launch(void* const* d_in, const int* in_sizes, int n_in,
                              void* d_out, int out_size)
{
    const float* z  = (const float*)d_in[0];
    const float* Wt = (const float*)d_in[1];
    const float* g  = (const float*)d_in[2];
    float* out = (float*)d_out;

    gumbel_fused_kernel<<<NGRP, 512>>>(z, Wt, g, out);
}